// round 9
// baseline (speedup 1.0000x reference)
#include <cuda_runtime.h>
#include <cuda_fp16.h>
#include <math.h>
#include <stdint.h>

// Problem shape (fixed)
#define BB 8
#define NN 2048
#define MM 2048
#define DD 256

#define TOT (BB * NN * DD)
#define NMT 8                        // number of M tiles (partials per row)

// fp16-split scratch (hi = fp16-rn(x), lo = fp16-rn(x - hi))
__device__ __align__(16) __half g_Ah[TOT];
__device__ __align__(16) __half g_Al[TOT];
__device__ __align__(16) __half g_Bh[TOT];
__device__ __align__(16) __half g_Bl[TOT];
__device__ float g_invx[BB * NN];
__device__ float g_invy[BB * MM];
// per-(row, mtile) partial argmax
__device__ float g_pmax[BB * NN * NMT];
__device__ int   g_pidx[BB * NN * NMT];

// ---------------------------------------------------------------------------
// PTX helpers (baseline sm_80-class; valid on plain sm_103 target)
// ---------------------------------------------------------------------------
__device__ __forceinline__ uint32_t smem_u32(const void* p) {
    uint32_t a;
    asm("{ .reg .u64 t; cvta.to.shared.u64 t, %1; cvt.u32.u64 %0, t; }"
        : "=r"(a) : "l"(p));
    return a;
}
#define CP16(sm, gp) \
    asm volatile("cp.async.cg.shared.global [%0], [%1], 16;" \
                 :: "r"(sm), "l"(gp) : "memory")
#define CP_WAIT_ALL() asm volatile("cp.async.wait_all;" ::: "memory")

__device__ __forceinline__ void ldm4(uint32_t* r, uint32_t addr) {
    asm volatile("ldmatrix.sync.aligned.m8n8.x4.shared.b16 {%0,%1,%2,%3}, [%4];"
        : "=r"(r[0]), "=r"(r[1]), "=r"(r[2]), "=r"(r[3]) : "r"(addr));
}
// m16n8k16 fp16 MMA, fp32 accumulate
__device__ __forceinline__ void mma_f16(float* d, const uint32_t* a, const uint32_t* b) {
    asm volatile("mma.sync.aligned.m16n8k16.row.col.f32.f16.f16.f32 "
        "{%0,%1,%2,%3}, {%4,%5,%6,%7}, {%8,%9}, {%0,%1,%2,%3};"
        : "+f"(d[0]), "+f"(d[1]), "+f"(d[2]), "+f"(d[3])
        : "r"(a[0]), "r"(a[1]), "r"(a[2]), "r"(a[3]), "r"(b[0]), "r"(b[1]));
}

// ---------------------------------------------------------------------------
// Kernel 1: fused per-row norm + fp16 split. One warp per row (256 floats).
// ---------------------------------------------------------------------------
__global__ void prep_kernel(const float* __restrict__ src,
                            const float* __restrict__ dst) {
    int gwarp = (blockIdx.x * blockDim.x + threadIdx.x) >> 5;
    int lane  = threadIdx.x & 31;
    const int total = BB * NN + BB * MM;
    if (gwarp >= total) return;

    const float* p;
    float* outp;
    __half *ho, *lo;
    size_t ro;
    if (gwarp < BB * NN) {
        ro = (size_t)gwarp * DD;
        p = src + ro; ho = g_Ah + ro; lo = g_Al + ro; outp = &g_invx[gwarp];
    } else {
        int r = gwarp - BB * NN;
        ro = (size_t)r * DD;
        p = dst + ro; ho = g_Bh + ro; lo = g_Bl + ro; outp = &g_invy[r];
    }
    float s = 0.0f;
#pragma unroll
    for (int h = 0; h < 2; h++) {
        float4 v = ((const float4*)p)[lane + 32 * h];
        s += v.x * v.x + v.y * v.y + v.z * v.z + v.w * v.w;
        __half hx = __float2half_rn(v.x);
        __half hy = __float2half_rn(v.y);
        __half hz = __float2half_rn(v.z);
        __half hw = __float2half_rn(v.w);
        __half lx = __float2half_rn(v.x - __half2float(hx));
        __half ly = __float2half_rn(v.y - __half2float(hy));
        __half lz = __float2half_rn(v.z - __half2float(hz));
        __half lw = __float2half_rn(v.w - __half2float(hw));
        __half2* hop = (__half2*)(ho + lane * 4 + h * 128);
        __half2* lop = (__half2*)(lo + lane * 4 + h * 128);
        hop[0] = __halves2half2(hx, hy);
        hop[1] = __halves2half2(hz, hw);
        lop[0] = __halves2half2(lx, ly);
        lop[1] = __halves2half2(lz, lw);
    }
#pragma unroll
    for (int o = 16; o > 0; o >>= 1) s += __shfl_xor_sync(0xffffffffu, s, o);
    if (lane == 0) *outp = 1.0f / fmaxf(sqrtf(s), 1e-12f);
}

// ---------------------------------------------------------------------------
// Kernel 2: fp16 HMMA (3-term split) tile GEMM + per-tile argmax partial.
// One CTA = one 128(n) x 256(m) x 256(K) tile; grid 8(mt) x 16(nt) x 8(b).
// 512 threads = 16 warps (2(n) x 8(m)); warp tile 64(n) x 32(m); 1 CTA/SM.
// K streamed in 4 chunks of 64 halves (128B rows, SW128); double-buffered.
// ---------------------------------------------------------------------------
#define AH_OFF 0
#define AL_OFF 16384
#define BH_OFF 32768
#define BL_OFF 65536
#define STAGE_B 98304
#define SMEM_SZ (2 * STAGE_B)           // 196608

__global__ __launch_bounds__(512, 1)
void match_kernel() {
    extern __shared__ char smem[];
    const uint32_t sb = smem_u32(smem);
    const int tid  = threadIdx.x;
    const int wid  = tid >> 5;
    const int lane = tid & 31;
    const int mtIdx = blockIdx.x;
    const int mt   = mtIdx * 256;
    const int n0   = blockIdx.y * 128;
    const int b    = blockIdx.z;
    const int warpN = wid >> 3;        // 0..1 -> n offset 64*warpN
    const int warpM = wid & 7;         // 0..7 -> m offset 32*warpM

    // global byte pointers (rows are 512B = 256 halves)
    const char* Ahp = (const char*)g_Ah + ((size_t)b * NN + n0) * 512;
    const char* Alp = (const char*)g_Al + ((size_t)b * NN + n0) * 512;
    const char* Bhp = (const char*)g_Bh + ((size_t)b * MM + mt) * 512;
    const char* Blp = (const char*)g_Bl + ((size_t)b * MM + mt) * 512;
    const float* invy_b = &g_invy[b * MM + mt];

    // --- staging geometry (per chunk: A 128x128B, B 256x128B, each h+l) ---
    // A: 1024 16B-units per h/l -> 2 per thread; B: 2048 -> 4 per thread
    int aswo[2], ago[2];
#pragma unroll
    for (int r = 0; r < 2; r++) {
        int id = tid + 512 * r;
        int row = id >> 3, c4 = id & 7;
        aswo[r] = row * 128 + ((c4 ^ (row & 7)) << 4);
        ago[r]  = row * 512 + c4 * 16;
    }
    int bswo[4], bgo[4];
#pragma unroll
    for (int r = 0; r < 4; r++) {
        int id = tid + 512 * r;
        int row = id >> 3, c4 = id & 7;
        bswo[r] = row * 128 + ((c4 ^ (row & 7)) << 4);
        bgo[r]  = row * 512 + c4 * 16;
    }

    // --- ldmatrix fragment addresses (fp16 m16n8k16) ---
    const int aRow = lane & 15;
    const int aK16 = lane >> 4;            // +16B for k8-15
    int aBase[4], aXor[4];
#pragma unroll
    for (int i = 0; i < 4; i++)
        aBase[i] = (warpN * 64 + i * 16 + aRow) * 128;
    const int bRow = ((lane >> 4) << 3) + (lane & 7);
    const int bK16 = (lane >> 3) & 1;
    int bBase[2], bXor[4];
#pragma unroll
    for (int t = 0; t < 2; t++)
        bBase[t] = (warpM * 32 + t * 16 + bRow) * 128;
#pragma unroll
    for (int s = 0; s < 4; s++) {          // s = k-step of 16 halves (32B)
        aXor[s] = (((s * 2 + aK16) ^ (aRow & 7)) << 4);
        bXor[s] = (((s * 2 + bK16) ^ (bRow & 7)) << 4);
    }

    // --- prologue: stage chunk 0 into buf0 ---
    {
        const uint32_t db = sb;
#pragma unroll
        for (int r = 0; r < 2; r++) {
            CP16(db + AH_OFF + aswo[r], Ahp + ago[r]);
            CP16(db + AL_OFF + aswo[r], Alp + ago[r]);
        }
#pragma unroll
        for (int r = 0; r < 4; r++) {
            CP16(db + BH_OFF + bswo[r], Bhp + bgo[r]);
            CP16(db + BL_OFF + bswo[r], Blp + bgo[r]);
        }
    }
    CP_WAIT_ALL();
    __syncthreads();

    float acc[4][4][4];
#pragma unroll
    for (int i = 0; i < 4; i++)
#pragma unroll
        for (int j = 0; j < 4; j++)
#pragma unroll
            for (int d = 0; d < 4; d++) acc[i][j][d] = 0.0f;

    for (int c = 0; c < 4; c++) {          // 4 chunks of 64 K-halves
        const int p = c & 1;
        // stage next chunk
        if (c < 3) {
            const int nko = (c + 1) * 128;  // byte offset within 512B row
            const uint32_t db = sb + ((c + 1) & 1) * STAGE_B;
#pragma unroll
            for (int r = 0; r < 2; r++) {
                CP16(db + AH_OFF + aswo[r], Ahp + ago[r] + nko);
                CP16(db + AL_OFF + aswo[r], Alp + ago[r] + nko);
            }
#pragma unroll
            for (int r = 0; r < 4; r++) {
                CP16(db + BH_OFF + bswo[r], Bhp + bgo[r] + nko);
                CP16(db + BL_OFF + bswo[r], Blp + bgo[r] + nko);
            }
        }
        // compute on buf p
        const uint32_t bb = sb + p * STAGE_B;
#pragma unroll
        for (int s = 0; s < 4; s++) {
            uint32_t bh[2][4], bl[2][4];
#pragma unroll
            for (int t = 0; t < 2; t++) {
                ldm4(bh[t], bb + BH_OFF + bBase[t] + bXor[s]);
                ldm4(bl[t], bb + BL_OFF + bBase[t] + bXor[s]);
            }
            {   // hi-A terms: hh + hl   (ah dies before al loads)
                uint32_t ah[4][4];
#pragma unroll
                for (int i = 0; i < 4; i++)
                    ldm4(ah[i], bb + AH_OFF + aBase[i] + aXor[s]);
#pragma unroll
                for (int i = 0; i < 4; i++)
#pragma unroll
                    for (int j = 0; j < 4; j++) {
                        mma_f16(acc[i][j], ah[i], &bh[j >> 1][(j & 1) * 2]);
                        mma_f16(acc[i][j], ah[i], &bl[j >> 1][(j & 1) * 2]);
                    }
            }
            {   // lo-A term: lh
                uint32_t al[4][4];
#pragma unroll
                for (int i = 0; i < 4; i++)
                    ldm4(al[i], bb + AL_OFF + aBase[i] + aXor[s]);
#pragma unroll
                for (int i = 0; i < 4; i++)
#pragma unroll
                    for (int j = 0; j < 4; j++)
                        mma_f16(acc[i][j], al[i], &bh[j >> 1][(j & 1) * 2]);
            }
        }
        CP_WAIT_ALL();
        __syncthreads();
    }

    // --- epilogue: per-thread argmax over this tile's m-cols ---
    // thread owns 8 rows: (i, half) -> warpN*64 + i*16 + half*8 + (lane>>2)
    float best[8];
    int   bidx[8];
#pragma unroll
    for (int k = 0; k < 8; k++) { best[k] = -1e30f; bidx[k] = 0; }

#pragma unroll
    for (int j = 0; j < 4; j++) {
        const int mc = warpM * 32 + j * 8 + 2 * (lane & 3);
        const int gm = mt + mc;
        const float2 iv2 = __ldg((const float2*)(invy_b + mc));
#pragma unroll
        for (int i = 0; i < 4; i++) {
            const int k0 = i * 2, k1 = i * 2 + 1;
            float v0 = acc[i][j][0] * iv2.x;
            float v1 = acc[i][j][1] * iv2.y;
            float v2 = acc[i][j][2] * iv2.x;
            float v3 = acc[i][j][3] * iv2.y;
            if (v0 > best[k0]) { best[k0] = v0; bidx[k0] = gm; }
            if (v1 > best[k0]) { best[k0] = v1; bidx[k0] = gm + 1; }
            if (v2 > best[k1]) { best[k1] = v2; bidx[k1] = gm; }
            if (v3 > best[k1]) { best[k1] = v3; bidx[k1] = gm + 1; }
        }
    }

    // reduce across the 4 lanes sharing each row (lane&3 varies)
#pragma unroll
    for (int s = 1; s < 4; s <<= 1) {
#pragma unroll
        for (int k = 0; k < 8; k++) {
            float ov = __shfl_xor_sync(0xffffffffu, best[k], s);
            int   oi = __shfl_xor_sync(0xffffffffu, bidx[k], s);
            if (ov > best[k] || (ov == best[k] && oi < bidx[k])) {
                best[k] = ov; bidx[k] = oi;
            }
        }
    }

    // cross-warpM reduce via smem (stage buffers are dead; synced above)
    float (*sb_best)[128] = (float(*)[128])(smem);
    int   (*sb_idx)[128]  = (int(*)[128])(smem + 4096);
    if ((lane & 3) == 0) {
#pragma unroll
        for (int k = 0; k < 8; k++) {
            int row = warpN * 64 + (k >> 1) * 16 + (k & 1) * 8 + (lane >> 2);
            sb_best[warpM][row] = best[k];
            sb_idx[warpM][row]  = bidx[k];
        }
    }
    __syncthreads();

    if (tid < 128) {
        float fb = sb_best[0][tid];
        int   fi = sb_idx[0][tid];
#pragma unroll
        for (int w = 1; w < 8; w++) {
            float ov = sb_best[w][tid];
            int   oi = sb_idx[w][tid];
            if (ov > fb || (ov == fb && oi < fi)) { fb = ov; fi = oi; }
        }
        const int gi = b * NN + n0 + tid;
        g_pmax[gi * NMT + mtIdx] = fb;
        g_pidx[gi * NMT + mtIdx] = fi;
    }
}

// ---------------------------------------------------------------------------
// Kernel 3: reduce 8 partials per row (ascending mt -> first-max wins),
// scale by invx, gather matched points.
// ---------------------------------------------------------------------------
__global__ void final_kernel(const float* __restrict__ pts,
                             float* __restrict__ out) {
    const int r = blockIdx.x * blockDim.x + threadIdx.x;   // 0..16383
    if (r >= BB * NN) return;
    float fb = -1e30f;
    int   fi = 0;
#pragma unroll
    for (int t = 0; t < NMT; t++) {
        float v = g_pmax[r * NMT + t];
        int   i = g_pidx[r * NMT + t];
        if (v > fb || (v == fb && i < fi)) { fb = v; fi = i; }
    }
    const int b = r >> 11;
    out[(size_t)BB * NN * 2 + r] = fb * g_invx[r];          // confidence
    const float* pp = pts + ((size_t)b * MM + fi) * 2;
    out[(size_t)r * 2 + 0] = pp[0];                          // matched x
    out[(size_t)r * 2 + 1] = pp[1];                          // matched y
}

// ---------------------------------------------------------------------------
extern "C" void kernel_launch(void* const* d_in, const int* in_sizes, int n_in,
                              void* d_out, int out_size) {
    const float* desc_src   = (const float*)d_in[0];
    const float* desc_dst   = (const float*)d_in[1];
    const float* points_dst = (const float*)d_in[2];
    float* out = (float*)d_out;

    cudaFuncSetAttribute(match_kernel,
                         cudaFuncAttributeMaxDynamicSharedMemorySize, SMEM_SZ);

    const int total_rows = BB * NN + BB * MM;   // 32768 rows, 1 warp each
    prep_kernel<<<(total_rows + 7) / 8, 256>>>(desc_src, desc_dst);

    dim3 grid(NMT, NN / 128, BB);               // 8 x 16 x 8 = 1024 tiles
    match_kernel<<<grid, 512, SMEM_SZ>>>();

    final_kernel<<<(BB * NN) / 256, 256>>>(points_dst, out);
}

// round 11
// speedup vs baseline: 1.0669x; 1.0669x over previous
#include <cuda_runtime.h>
#include <cuda_fp16.h>
#include <math.h>
#include <stdint.h>

// Problem shape (fixed)
#define BB 8
#define NN 2048
#define MM 2048
#define DD 256

#define TOT (BB * NN * DD)
#define NMT 16                       // number of M tiles (partials per row)

// fp16-split scratch (hi = fp16-rn(x), lo = fp16-rn(x - hi))
__device__ __align__(16) __half g_Ah[TOT];
__device__ __align__(16) __half g_Al[TOT];
__device__ __align__(16) __half g_Bh[TOT];
__device__ __align__(16) __half g_Bl[TOT];
__device__ float g_invx[BB * NN];
__device__ float g_invy[BB * MM];
// per-(row, mtile) partial argmax
__device__ float g_pmax[BB * NN * NMT];
__device__ int   g_pidx[BB * NN * NMT];

// ---------------------------------------------------------------------------
// PTX helpers (baseline sm_80-class; valid on plain sm_103 target)
// ---------------------------------------------------------------------------
__device__ __forceinline__ uint32_t smem_u32(const void* p) {
    uint32_t a;
    asm("{ .reg .u64 t; cvta.to.shared.u64 t, %1; cvt.u32.u64 %0, t; }"
        : "=r"(a) : "l"(p));
    return a;
}
#define CP16(sm, gp) \
    asm volatile("cp.async.cg.shared.global [%0], [%1], 16;" \
                 :: "r"(sm), "l"(gp) : "memory")
#define CP_WAIT_ALL() asm volatile("cp.async.wait_all;" ::: "memory")

__device__ __forceinline__ void ldm4(uint32_t* r, uint32_t addr) {
    asm volatile("ldmatrix.sync.aligned.m8n8.x4.shared.b16 {%0,%1,%2,%3}, [%4];"
        : "=r"(r[0]), "=r"(r[1]), "=r"(r[2]), "=r"(r[3]) : "r"(addr));
}
// m16n8k16 fp16 MMA, fp32 accumulate
__device__ __forceinline__ void mma_f16(float* d, const uint32_t* a, const uint32_t* b) {
    asm volatile("mma.sync.aligned.m16n8k16.row.col.f32.f16.f16.f32 "
        "{%0,%1,%2,%3}, {%4,%5,%6,%7}, {%8,%9}, {%0,%1,%2,%3};"
        : "+f"(d[0]), "+f"(d[1]), "+f"(d[2]), "+f"(d[3])
        : "r"(a[0]), "r"(a[1]), "r"(a[2]), "r"(a[3]), "r"(b[0]), "r"(b[1]));
}

// ---------------------------------------------------------------------------
// Kernel 1: fused per-row norm + fp16 split. One warp per row (256 floats).
// ---------------------------------------------------------------------------
__global__ void prep_kernel(const float* __restrict__ src,
                            const float* __restrict__ dst) {
    int gwarp = (blockIdx.x * blockDim.x + threadIdx.x) >> 5;
    int lane  = threadIdx.x & 31;
    const int total = BB * NN + BB * MM;
    if (gwarp >= total) return;

    const float* p;
    float* outp;
    __half *ho, *lo;
    size_t ro;
    if (gwarp < BB * NN) {
        ro = (size_t)gwarp * DD;
        p = src + ro; ho = g_Ah + ro; lo = g_Al + ro; outp = &g_invx[gwarp];
    } else {
        int r = gwarp - BB * NN;
        ro = (size_t)r * DD;
        p = dst + ro; ho = g_Bh + ro; lo = g_Bl + ro; outp = &g_invy[r];
    }
    float s = 0.0f;
#pragma unroll
    for (int h = 0; h < 2; h++) {
        float4 v = ((const float4*)p)[lane + 32 * h];
        s += v.x * v.x + v.y * v.y + v.z * v.z + v.w * v.w;
        __half hx = __float2half_rn(v.x);
        __half hy = __float2half_rn(v.y);
        __half hz = __float2half_rn(v.z);
        __half hw = __float2half_rn(v.w);
        __half lx = __float2half_rn(v.x - __half2float(hx));
        __half ly = __float2half_rn(v.y - __half2float(hy));
        __half lz = __float2half_rn(v.z - __half2float(hz));
        __half lw = __float2half_rn(v.w - __half2float(hw));
        __half2* hop = (__half2*)(ho + lane * 4 + h * 128);
        __half2* lop = (__half2*)(lo + lane * 4 + h * 128);
        hop[0] = __halves2half2(hx, hy);
        hop[1] = __halves2half2(hz, hw);
        lop[0] = __halves2half2(lx, ly);
        lop[1] = __halves2half2(lz, lw);
    }
#pragma unroll
    for (int o = 16; o > 0; o >>= 1) s += __shfl_xor_sync(0xffffffffu, s, o);
    if (lane == 0) *outp = 1.0f / fmaxf(sqrtf(s), 1e-12f);
}

// ---------------------------------------------------------------------------
// Kernel 2: fp16 HMMA (3-term split) tile GEMM + per-tile argmax partial.
// One CTA = one 64(n) x 128(m) x 256(K) tile; grid 16(mt) x 32(nt) x 8(b).
// 128 threads = 4 warps, ALL at warpN=0; warp tile 64(n) x 32(m).
// 2 CTAs/SM (96KB smem each). K in 4 chunks of 64 halves; double-buffered.
// ---------------------------------------------------------------------------
#define AH_OFF 0
#define AL_OFF 8192
#define BH_OFF 16384
#define BL_OFF 32768
#define STAGE_B 49152
#define SMEM_SZ (2 * STAGE_B)           // 98304 -> 2 CTAs/SM
#define NTHR 128

__global__ __launch_bounds__(NTHR, 2)
void match_kernel() {
    extern __shared__ char smem[];
    const uint32_t sb = smem_u32(smem);
    const int tid  = threadIdx.x;
    const int wid  = tid >> 5;          // 0..3 = warpM
    const int lane = tid & 31;
    const int mtIdx = blockIdx.x;
    const int mt   = mtIdx * 128;
    const int n0   = blockIdx.y * 64;
    const int b    = blockIdx.z;
    const int warpM = wid;              // m offset 32*warpM

    // global byte pointers (rows are 512B = 256 halves)
    const char* Ahp = (const char*)g_Ah + ((size_t)b * NN + n0) * 512;
    const char* Alp = (const char*)g_Al + ((size_t)b * NN + n0) * 512;
    const char* Bhp = (const char*)g_Bh + ((size_t)b * MM + mt) * 512;
    const char* Blp = (const char*)g_Bl + ((size_t)b * MM + mt) * 512;
    const float* invy_b = &g_invy[b * MM + mt];

    // --- staging geometry (per chunk: A 64x128B, B 128x128B, each h+l) ---
    // A: 512 16B-units per h/l -> 4 per thread; B: 1024 -> 8 per thread
    int aswo[4], ago[4];
#pragma unroll
    for (int r = 0; r < 4; r++) {
        int id = tid + NTHR * r;
        int row = id >> 3, c4 = id & 7;
        aswo[r] = row * 128 + ((c4 ^ (row & 7)) << 4);
        ago[r]  = row * 512 + c4 * 16;
    }
    int bswo[8], bgo[8];
#pragma unroll
    for (int r = 0; r < 8; r++) {
        int id = tid + NTHR * r;
        int row = id >> 3, c4 = id & 7;
        bswo[r] = row * 128 + ((c4 ^ (row & 7)) << 4);
        bgo[r]  = row * 512 + c4 * 16;
    }

    // --- ldmatrix fragment addresses (fp16 m16n8k16) ---
    const int aRow = lane & 15;
    const int aK16 = lane >> 4;            // +16B for k8-15
    int aBase[4], aXor[4];
#pragma unroll
    for (int i = 0; i < 4; i++)
        aBase[i] = (i * 16 + aRow) * 128;  // 64 n-rows, warpN = 0
    const int bRow = ((lane >> 4) << 3) + (lane & 7);
    const int bK16 = (lane >> 3) & 1;
    int bBase[2], bXor[4];
#pragma unroll
    for (int t = 0; t < 2; t++)
        bBase[t] = (warpM * 32 + t * 16 + bRow) * 128;
#pragma unroll
    for (int s = 0; s < 4; s++) {          // s = k-step of 16 halves (32B)
        aXor[s] = (((s * 2 + aK16) ^ (aRow & 7)) << 4);
        bXor[s] = (((s * 2 + bK16) ^ (bRow & 7)) << 4);
    }

    // --- prologue: stage chunk 0 into buf0 ---
    {
        const uint32_t db = sb;
#pragma unroll
        for (int r = 0; r < 4; r++) {
            CP16(db + AH_OFF + aswo[r], Ahp + ago[r]);
            CP16(db + AL_OFF + aswo[r], Alp + ago[r]);
        }
#pragma unroll
        for (int r = 0; r < 8; r++) {
            CP16(db + BH_OFF + bswo[r], Bhp + bgo[r]);
            CP16(db + BL_OFF + bswo[r], Blp + bgo[r]);
        }
    }
    CP_WAIT_ALL();
    __syncthreads();

    float acc[4][4][4];
#pragma unroll
    for (int i = 0; i < 4; i++)
#pragma unroll
        for (int j = 0; j < 4; j++)
#pragma unroll
            for (int d = 0; d < 4; d++) acc[i][j][d] = 0.0f;

    for (int c = 0; c < 4; c++) {          // 4 chunks of 64 K-halves
        const int p = c & 1;
        // stage next chunk
        if (c < 3) {
            const int nko = (c + 1) * 128;  // byte offset within 512B row
            const uint32_t db = sb + ((c + 1) & 1) * STAGE_B;
#pragma unroll
            for (int r = 0; r < 4; r++) {
                CP16(db + AH_OFF + aswo[r], Ahp + ago[r] + nko);
                CP16(db + AL_OFF + aswo[r], Alp + ago[r] + nko);
            }
#pragma unroll
            for (int r = 0; r < 8; r++) {
                CP16(db + BH_OFF + bswo[r], Bhp + bgo[r] + nko);
                CP16(db + BL_OFF + bswo[r], Blp + bgo[r] + nko);
            }
        }
        // compute on buf p
        const uint32_t bb = sb + p * STAGE_B;
#pragma unroll
        for (int s = 0; s < 4; s++) {
            uint32_t bh[2][4], bl[2][4];
#pragma unroll
            for (int t = 0; t < 2; t++) {
                ldm4(bh[t], bb + BH_OFF + bBase[t] + bXor[s]);
                ldm4(bl[t], bb + BL_OFF + bBase[t] + bXor[s]);
            }
            {   // hi-A terms: hh + hl   (ah dies before al loads)
                uint32_t ah[4][4];
#pragma unroll
                for (int i = 0; i < 4; i++)
                    ldm4(ah[i], bb + AH_OFF + aBase[i] + aXor[s]);
#pragma unroll
                for (int i = 0; i < 4; i++)
#pragma unroll
                    for (int j = 0; j < 4; j++) {
                        mma_f16(acc[i][j], ah[i], &bh[j >> 1][(j & 1) * 2]);
                        mma_f16(acc[i][j], ah[i], &bl[j >> 1][(j & 1) * 2]);
                    }
            }
            {   // lo-A term: lh
                uint32_t al[4][4];
#pragma unroll
                for (int i = 0; i < 4; i++)
                    ldm4(al[i], bb + AL_OFF + aBase[i] + aXor[s]);
#pragma unroll
                for (int i = 0; i < 4; i++)
#pragma unroll
                    for (int j = 0; j < 4; j++)
                        mma_f16(acc[i][j], al[i], &bh[j >> 1][(j & 1) * 2]);
            }
        }
        CP_WAIT_ALL();
        __syncthreads();
    }

    // --- epilogue: per-thread argmax over this tile's m-cols ---
    // thread owns 8 rows: (i, half) -> i*16 + half*8 + (lane>>2)
    float best[8];
    int   bidx[8];
#pragma unroll
    for (int k = 0; k < 8; k++) { best[k] = -1e30f; bidx[k] = 0; }

#pragma unroll
    for (int j = 0; j < 4; j++) {
        const int mc = warpM * 32 + j * 8 + 2 * (lane & 3);
        const int gm = mt + mc;
        const float2 iv2 = __ldg((const float2*)(invy_b + mc));
#pragma unroll
        for (int i = 0; i < 4; i++) {
            const int k0 = i * 2, k1 = i * 2 + 1;
            float v0 = acc[i][j][0] * iv2.x;
            float v1 = acc[i][j][1] * iv2.y;
            float v2 = acc[i][j][2] * iv2.x;
            float v3 = acc[i][j][3] * iv2.y;
            if (v0 > best[k0]) { best[k0] = v0; bidx[k0] = gm; }
            if (v1 > best[k0]) { best[k0] = v1; bidx[k0] = gm + 1; }
            if (v2 > best[k1]) { best[k1] = v2; bidx[k1] = gm; }
            if (v3 > best[k1]) { best[k1] = v3; bidx[k1] = gm + 1; }
        }
    }

    // reduce across the 4 lanes sharing each row (lane&3 varies)
#pragma unroll
    for (int s = 1; s < 4; s <<= 1) {
#pragma unroll
        for (int k = 0; k < 8; k++) {
            float ov = __shfl_xor_sync(0xffffffffu, best[k], s);
            int   oi = __shfl_xor_sync(0xffffffffu, bidx[k], s);
            if (ov > best[k] || (ov == best[k] && oi < bidx[k])) {
                best[k] = ov; bidx[k] = oi;
            }
        }
    }

    // cross-warp reduce via smem (stage buffers dead; last sync above)
    float (*sb_best)[64] = (float(*)[64])(smem);
    int   (*sb_idx)[64]  = (int(*)[64])(smem + 2048);
    if ((lane & 3) == 0) {
#pragma unroll
        for (int k = 0; k < 8; k++) {
            int row = (k >> 1) * 16 + (k & 1) * 8 + (lane >> 2);
            sb_best[warpM][row] = best[k];
            sb_idx[warpM][row]  = bidx[k];
        }
    }
    __syncthreads();

    if (tid < 64) {
        float fb = sb_best[0][tid];
        int   fi = sb_idx[0][tid];
#pragma unroll
        for (int w = 1; w < 4; w++) {
            float ov = sb_best[w][tid];
            int   oi = sb_idx[w][tid];
            if (ov > fb || (ov == fb && oi < fi)) { fb = ov; fi = oi; }
        }
        const int gi = b * NN + n0 + tid;
        g_pmax[gi * NMT + mtIdx] = fb;
        g_pidx[gi * NMT + mtIdx] = fi;
    }
}

// ---------------------------------------------------------------------------
// Kernel 3: reduce 16 partials per row (ascending mt -> first-max wins),
// scale by invx, gather matched points.
// ---------------------------------------------------------------------------
__global__ void final_kernel(const float* __restrict__ pts,
                             float* __restrict__ out) {
    const int r = blockIdx.x * blockDim.x + threadIdx.x;   // 0..16383
    if (r >= BB * NN) return;
    float fb = -1e30f;
    int   fi = 0;
#pragma unroll
    for (int t = 0; t < NMT; t++) {
        float v = g_pmax[r * NMT + t];
        int   i = g_pidx[r * NMT + t];
        if (v > fb || (v == fb && i < fi)) { fb = v; fi = i; }
    }
    const int b = r >> 11;
    out[(size_t)BB * NN * 2 + r] = fb * g_invx[r];          // confidence
    const float* pp = pts + ((size_t)b * MM + fi) * 2;
    out[(size_t)r * 2 + 0] = pp[0];                          // matched x
    out[(size_t)r * 2 + 1] = pp[1];                          // matched y
}

// ---------------------------------------------------------------------------
extern "C" void kernel_launch(void* const* d_in, const int* in_sizes, int n_in,
                              void* d_out, int out_size) {
    const float* desc_src   = (const float*)d_in[0];
    const float* desc_dst   = (const float*)d_in[1];
    const float* points_dst = (const float*)d_in[2];
    float* out = (float*)d_out;

    cudaFuncSetAttribute(match_kernel,
                         cudaFuncAttributeMaxDynamicSharedMemorySize, SMEM_SZ);

    const int total_rows = BB * NN + BB * MM;   // 32768 rows, 1 warp each
    prep_kernel<<<(total_rows + 7) / 8, 256>>>(desc_src, desc_dst);

    dim3 grid(NMT, NN / 64, BB);                // 16 x 32 x 8 = 4096 tiles
    match_kernel<<<grid, NTHR, SMEM_SZ>>>();

    final_kernel<<<(BB * NN) / 256, 256>>>(points_dst, out);
}